// round 4
// baseline (speedup 1.0000x reference)
#include <cuda_runtime.h>
#include <cstdint>

// CorticalSheet fixed-degree SpMM
//   out[n,b] = sum_k values[n,k] * x[indices[n,k], b] + bias[n]
// N = 1,000,000 (derived at runtime from in_sizes), K = 32, B = 8
//
// One warp per neuron:
//   - Each lane pre-loads its own indices[n,lane] and values[n,lane]
//     (two perfectly coalesced 128B transactions per warp, evict-first).
//   - Lane layout: lane = kgroup*8 + b (kgroup in 0..3, b in 0..7).
//     Per unrolled step, 4 k-slots are processed; the 8 lanes sharing a
//     kgroup read 8 consecutive floats of one x row = exactly one 32B L2
//     sector per gathered row, 4 sectors (128B) per gather instruction.
//   - k index/value broadcast via __shfl_sync from pre-loaded registers.
//   - Reduction over the 4 kgroups: two shfl_xor steps; lanes 0..7 write
//     the 8 outputs (one 32B sector store per neuron).

#define KK 32
#define BB 8

__global__ __launch_bounds__(256, 8)
void cortical_spmm_kernel(const float*  __restrict__ x,
                          const float*  __restrict__ values,
                          const float*  __restrict__ bias,
                          const int*    __restrict__ indices,
                          float*        __restrict__ out,
                          int N)
{
    const unsigned FULL = 0xffffffffu;
    const int warp_global = (int)((blockIdx.x * (unsigned)blockDim.x + threadIdx.x) >> 5);
    if (warp_global >= N) return;
    const int n    = warp_global;
    const int lane = (int)(threadIdx.x & 31u);

    // Start the bias load early (all lanes hit the same address -> broadcast);
    // overlaps with the gather dependency chain.
    const float bn = __ldg(bias + n);

    // Coalesced streaming loads of this neuron's synapse data (evict-first:
    // keep L2 capacity for the x gather table).
    const int   idx_mine = __ldcs(indices + (size_t)n * KK + lane);
    const float val_mine = __ldcs(values  + (size_t)n * KK + lane);

    const int kgroup = lane >> 3;   // 0..3
    const int b      = lane & 7;    // 0..7

    float acc = 0.0f;
#pragma unroll
    for (int step = 0; step < 8; ++step) {
        const int   k   = step * 4 + kgroup;
        const int   idx = __shfl_sync(FULL, idx_mine, k);
        const float v   = __shfl_sync(FULL, val_mine, k);
        const float xv  = __ldg(x + (size_t)idx * BB + b);
        acc = fmaf(v, xv, acc);
    }

    // Reduce across the 4 kgroups (lanes b, b+8, b+16, b+24).
    acc += __shfl_xor_sync(FULL, acc, 8);
    acc += __shfl_xor_sync(FULL, acc, 16);

    if (lane < 8) {
        out[(size_t)n * BB + b] = acc + bn;
    }
}

extern "C" void kernel_launch(void* const* d_in, const int* in_sizes, int n_in,
                              void* d_out, int out_size)
{
    // metadata order: x [N*B] f32, values [N*K] f32, bias [N] f32, indices [N*K] i32
    const float* x       = (const float*)d_in[0];
    const float* values  = (const float*)d_in[1];
    const float* bias    = (const float*)d_in[2];
    const int*   indices = (const int*)d_in[3];
    float*       out     = (float*)d_out;

    const int N = in_sizes[2];  // bias element count == number of neurons

    // One warp per neuron: N warps total, 8 warps (256 threads) per block.
    const int threads = 256;
    const int warps_per_block = threads / 32;
    const int blocks = (N + warps_per_block - 1) / warps_per_block;

    cortical_spmm_kernel<<<blocks, threads>>>(x, values, bias, indices, out, N);
}